// round 2
// baseline (speedup 1.0000x reference)
#include <cuda_runtime.h>
#include <cstddef>

#define NMAX 100000
#define FDIM 128

// ---- static device scratch (no allocations allowed) ----
__device__ float g_dinv[NMAX];                    // deg -> dinv in place
__device__ float g_agg[NMAX * FDIM];              // scatter accumulator
__device__ float g_xt1[NMAX * 384];               // [X0|X1|X2] layer 1
__device__ float g_xt2[NMAX * 384];               // [X0|X1|X2] layer 2 (col0 = layer1 output = residual)
__device__ float g_m1[NMAX * FDIM];               // x after layer2 (+res)
__device__ float g_m2[NMAX * FDIM];               // h = relu(x Wm1^T + bm1)

// ---------------- degree ----------------
__global__ void k_deg(const int* __restrict__ dst, int ne, float* __restrict__ deg) {
    int i = blockIdx.x * blockDim.x + threadIdx.x;
    if (i < ne) atomicAdd(&deg[dst[i]], 1.0f);
}

__global__ void k_dinv(float* __restrict__ d, int n) {
    int i = blockIdx.x * blockDim.x + threadIdx.x;
    if (i < n) {
        float v = fmaxf(d[i], 1.0f);
        d[i] = 1.0f / sqrtf(v);
    }
}

// ---------------- edge scatter:  agg[dst] += X[src] * dinv[src] ----------------
// one warp per edge; each lane handles one float4 (128 floats/row)
__global__ void k_scatter(const float* __restrict__ X, int ldx,
                          const int* __restrict__ src, const int* __restrict__ dst,
                          const float* __restrict__ dinv,
                          float* __restrict__ agg, int ne) {
    int e = blockIdx.x * (blockDim.x >> 5) + (threadIdx.x >> 5);
    if (e >= ne) return;
    int lane = threadIdx.x & 31;
    int s = src[e];
    int d = dst[e];
    float sc = __ldg(&dinv[s]);
    float4 v = *(const float4*)(X + (size_t)s * ldx + lane * 4);
    float* p = agg + (size_t)d * FDIM + lane * 4;
    asm volatile("red.global.add.v4.f32 [%0], {%1,%2,%3,%4};"
                 :: "l"(p), "f"(v.x * sc), "f"(v.y * sc), "f"(v.z * sc), "f"(v.w * sc)
                 : "memory");
}

// ---------------- X1 = agg*dinv - X0   (optionally copy X0 into Xt slot) ----------------
__global__ void k_x1(const float* __restrict__ X0, int ld0,
                     const float* __restrict__ agg,
                     const float* __restrict__ dinv,
                     float* __restrict__ X1, int ld1,
                     float* __restrict__ X0copy, int ldc,
                     int n) {
    int i = blockIdx.x * blockDim.x + threadIdx.x;
    if (i >= n * 32) return;
    int node = i >> 5;
    int c = (i & 31) * 4;
    float di = __ldg(&dinv[node]);
    float4 x0 = *(const float4*)(X0 + (size_t)node * ld0 + c);
    float4 a  = *(const float4*)(agg + (size_t)node * FDIM + c);
    float4 r;
    r.x = a.x * di - x0.x;
    r.y = a.y * di - x0.y;
    r.z = a.z * di - x0.z;
    r.w = a.w * di - x0.w;
    *(float4*)(X1 + (size_t)node * ld1 + c) = r;
    if (X0copy) *(float4*)(X0copy + (size_t)node * ldc + c) = x0;
}

// ---------------- X2 = 2*agg*dinv - 2*X1 - X0 ----------------
__global__ void k_x2(const float* __restrict__ X0, int ld0,
                     const float* __restrict__ X1, int ld1,
                     const float* __restrict__ agg,
                     const float* __restrict__ dinv,
                     float* __restrict__ X2, int ld2,
                     int n) {
    int i = blockIdx.x * blockDim.x + threadIdx.x;
    if (i >= n * 32) return;
    int node = i >> 5;
    int c = (i & 31) * 4;
    float di = 2.0f * __ldg(&dinv[node]);
    float4 x0 = *(const float4*)(X0 + (size_t)node * ld0 + c);
    float4 x1 = *(const float4*)(X1 + (size_t)node * ld1 + c);
    float4 a  = *(const float4*)(agg + (size_t)node * FDIM + c);
    float4 r;
    r.x = a.x * di - 2.0f * x1.x - x0.x;
    r.y = a.y * di - 2.0f * x1.y - x0.y;
    r.z = a.z * di - 2.0f * x1.z - x0.z;
    r.w = a.w * di - 2.0f * x1.w - x0.w;
    *(float4*)(X2 + (size_t)node * ld2 + c) = r;
}

// ---------------- SGEMM  C[M,BN] = A[M,K] * W[BN,K]^T  + fused epilogue ----------------
#define EPI_BIAS     0
#define EPI_RELU_BN  1
#define EPI_RELU_RES 2
#define EPI_RELU     3

template<int BN, int TN, int EPI>
__global__ __launch_bounds__(256)
void k_gemm(const float* __restrict__ A, int lda, int M, int K,
            const float* __restrict__ W,          // [BN, K] row-major (ld = K)
            const float* __restrict__ bias,       // [BN]
            const float* __restrict__ q0,         // gamma
            const float* __restrict__ q1,         // beta
            const float* __restrict__ q2,         // mean
            const float* __restrict__ q3,         // var
            const float* __restrict__ res, int ldres,
            float* __restrict__ C, int ldc) {
    constexpr int BM = 128, BK = 16, TM = 8;
    __shared__ float As[BK][BM];
    __shared__ float Bs[BK][BN];

    const int tid = threadIdx.x;
    const int m0 = blockIdx.x * BM;
    const int tx = tid % (BN / TN);
    const int ty = tid / (BN / TN);

    float acc[TM][TN];
    #pragma unroll
    for (int i = 0; i < TM; i++)
        #pragma unroll
        for (int j = 0; j < TN; j++) acc[i][j] = 0.0f;

    for (int kt = 0; kt < K; kt += BK) {
        // load A tile (BM x BK), store transposed As[k][m]
        #pragma unroll
        for (int i = tid; i < (BM * BK) / 4; i += 256) {
            int row = i >> 2;
            int kc = (i & 3) * 4;
            int gm = m0 + row;
            float4 v = make_float4(0.f, 0.f, 0.f, 0.f);
            if (gm < M) v = *(const float4*)(A + (size_t)gm * lda + kt + kc);
            As[kc + 0][row] = v.x;
            As[kc + 1][row] = v.y;
            As[kc + 2][row] = v.z;
            As[kc + 3][row] = v.w;
        }
        // load W tile (BN x BK), store transposed Bs[k][n]
        #pragma unroll
        for (int i = tid; i < (BN * BK) / 4; i += 256) {
            int row = i >> 2;
            int kc = (i & 3) * 4;
            float4 v = *(const float4*)(W + (size_t)row * K + kt + kc);
            Bs[kc + 0][row] = v.x;
            Bs[kc + 1][row] = v.y;
            Bs[kc + 2][row] = v.z;
            Bs[kc + 3][row] = v.w;
        }
        __syncthreads();
        #pragma unroll
        for (int kk = 0; kk < BK; kk++) {
            float a[TM], b[TN];
            #pragma unroll
            for (int i = 0; i < TM; i++) a[i] = As[kk][ty * TM + i];
            #pragma unroll
            for (int j = 0; j < TN; j++) b[j] = Bs[kk][tx * TN + j];
            #pragma unroll
            for (int i = 0; i < TM; i++)
                #pragma unroll
                for (int j = 0; j < TN; j++)
                    acc[i][j] += a[i] * b[j];
        }
        __syncthreads();
    }

    #pragma unroll
    for (int i = 0; i < TM; i++) {
        int m = m0 + ty * TM + i;
        if (m >= M) continue;
        #pragma unroll
        for (int j = 0; j < TN; j++) {
            int nn = tx * TN + j;
            float v = acc[i][j] + __ldg(&bias[nn]);
            if (EPI == EPI_RELU_BN) {
                v = fmaxf(v, 0.0f);
                v = (v - __ldg(&q2[nn])) * rsqrtf(__ldg(&q3[nn]) + 1e-5f) * __ldg(&q0[nn]) + __ldg(&q1[nn]);
            } else if (EPI == EPI_RELU_RES) {
                v = fmaxf(v, 0.0f) + __ldg(&res[(size_t)m * ldres + nn]);
            } else if (EPI == EPI_RELU) {
                v = fmaxf(v, 0.0f);
            }
            C[(size_t)m * ldc + nn] = v;
        }
    }
}

extern "C" void kernel_launch(void* const* d_in, const int* in_sizes, int n_in,
                              void* d_out, int out_size) {
    const float* feat  = (const float*)d_in[0];
    const int*   esrc  = (const int*)d_in[1];
    const int*   edst  = (const int*)d_in[2];
    const float* W1    = (const float*)d_in[3];
    const float* b1    = (const float*)d_in[4];
    const float* gamma = (const float*)d_in[5];
    const float* beta  = (const float*)d_in[6];
    const float* mean  = (const float*)d_in[7];
    const float* var   = (const float*)d_in[8];
    const float* W3    = (const float*)d_in[9];
    const float* b3    = (const float*)d_in[10];
    const float* Wm1   = (const float*)d_in[11];
    const float* bm1   = (const float*)d_in[12];
    const float* Wm2   = (const float*)d_in[13];
    const float* bm2   = (const float*)d_in[14];

    const int n  = in_sizes[0] / FDIM;
    const int ne = in_sizes[1];

    float *dinv, *agg, *xt1, *xt2, *m1, *m2;
    cudaGetSymbolAddress((void**)&dinv, g_dinv);
    cudaGetSymbolAddress((void**)&agg,  g_agg);
    cudaGetSymbolAddress((void**)&xt1,  g_xt1);
    cudaGetSymbolAddress((void**)&xt2,  g_xt2);
    cudaGetSymbolAddress((void**)&m1,   g_m1);
    cudaGetSymbolAddress((void**)&m2,   g_m2);

    const size_t aggBytes = (size_t)n * FDIM * sizeof(float);
    const int egrid = (ne + 7) / 8;           // 8 edges (warps) per 256-thread block
    const int vgrid = (n * 32 + 255) / 256;   // one float4 per thread
    const int ggrid = (n + 127) / 128;

    // degrees -> dinv
    cudaMemsetAsync(dinv, 0, (size_t)n * sizeof(float));
    k_deg<<<(ne + 255) / 256, 256>>>(edst, ne, dinv);
    k_dinv<<<(n + 255) / 256, 256>>>(dinv, n);

    // ---- Cheb layer 1 (X0 = features) ----
    cudaMemsetAsync(agg, 0, aggBytes);
    k_scatter<<<egrid, 256>>>(feat, FDIM, esrc, edst, dinv, agg, ne);
    k_x1<<<vgrid, 256>>>(feat, FDIM, agg, dinv, xt1 + 128, 384, xt1, 384, n);
    cudaMemsetAsync(agg, 0, aggBytes);
    k_scatter<<<egrid, 256>>>(xt1 + 128, 384, esrc, edst, dinv, agg, ne);
    k_x2<<<vgrid, 256>>>(xt1, 384, xt1 + 128, 384, agg, dinv, xt1 + 256, 384, n);
    // y = BN(relu(Xt1 @ W1^T + b1)) -> xt2[:, 0:128] (also the residual)
    k_gemm<128, 8, EPI_RELU_BN><<<ggrid, 256>>>(xt1, 384, n, 384, W1, b1,
                                                gamma, beta, mean, var,
                                                (const float*)nullptr, 0, xt2, 384);

    // ---- Cheb layer 2 (X0 = xt2[:, 0:128]) ----
    cudaMemsetAsync(agg, 0, aggBytes);
    k_scatter<<<egrid, 256>>>(xt2, 384, esrc, edst, dinv, agg, ne);
    k_x1<<<vgrid, 256>>>(xt2, 384, agg, dinv, xt2 + 128, 384, (float*)nullptr, 0, n);
    cudaMemsetAsync(agg, 0, aggBytes);
    k_scatter<<<egrid, 256>>>(xt2 + 128, 384, esrc, edst, dinv, agg, ne);
    k_x2<<<vgrid, 256>>>(xt2, 384, xt2 + 128, 384, agg, dinv, xt2 + 256, 384, n);
    // x = relu(Xt2 @ W3^T + b3) + residual -> m1
    k_gemm<128, 8, EPI_RELU_RES><<<ggrid, 256>>>(xt2, 384, n, 384, W3, b3,
                                                 (const float*)nullptr, (const float*)nullptr,
                                                 (const float*)nullptr, (const float*)nullptr,
                                                 xt2, 384, m1, 128);

    // ---- MLP head ----
    k_gemm<128, 8, EPI_RELU><<<ggrid, 256>>>(m1, 128, n, 128, Wm1, bm1,
                                             (const float*)nullptr, (const float*)nullptr,
                                             (const float*)nullptr, (const float*)nullptr,
                                             (const float*)nullptr, 0, m2, 128);
    k_gemm<64, 4, EPI_BIAS><<<ggrid, 256>>>(m2, 128, n, 128, Wm2, bm2,
                                            (const float*)nullptr, (const float*)nullptr,
                                            (const float*)nullptr, (const float*)nullptr,
                                            (const float*)nullptr, 0, (float*)d_out, 64);
}

// round 6
// speedup vs baseline: 1.7047x; 1.7047x over previous
#include <cuda_runtime.h>
#include <cstdint>
#include <cstddef>

#define NMAX 100000
#define FDIM 128

// ---- static device scratch (no allocations allowed) ----
__device__ float g_dinv[NMAX];
__device__ float g_agg[NMAX * FDIM];
__device__ float g_xt1[NMAX * 384];
__device__ float g_xt2[NMAX * 384];
__device__ float g_m1[NMAX * FDIM];
__device__ float g_m2[NMAX * FDIM];

__device__ __forceinline__ uint32_t f2tf32(float x) {
    uint32_t r;
    asm("cvt.rna.tf32.f32 %0, %1;" : "=r"(r) : "f"(x));
    return r;
}

// ======================= graph kernels =======================
__global__ void k_deg(const int* __restrict__ dst, int ne, float* __restrict__ deg) {
    int i = blockIdx.x * blockDim.x + threadIdx.x;
    if (i < ne) atomicAdd(&deg[dst[i]], 1.0f);
}

__global__ void k_dinv(float* __restrict__ d, int n) {
    int i = blockIdx.x * blockDim.x + threadIdx.x;
    if (i < n) {
        float v = fmaxf(d[i], 1.0f);
        d[i] = 1.0f / sqrtf(v);
    }
}

// agg[dst] += X[src] * dinv[src]; one warp per edge, one float4 per lane
__global__ void k_scatter(const float* __restrict__ X, int ldx,
                          const int* __restrict__ src, const int* __restrict__ dst,
                          const float* __restrict__ dinv,
                          float* __restrict__ agg, int ne) {
    int e = blockIdx.x * (blockDim.x >> 5) + (threadIdx.x >> 5);
    if (e >= ne) return;
    int lane = threadIdx.x & 31;
    int s = src[e];
    int d = dst[e];
    float sc = __ldg(&dinv[s]);
    float4 v = *(const float4*)(X + (size_t)s * ldx + lane * 4);
    float* p = agg + (size_t)d * FDIM + lane * 4;
    asm volatile("red.global.add.v4.f32 [%0], {%1,%2,%3,%4};"
                 :: "l"(p), "f"(v.x * sc), "f"(v.y * sc), "f"(v.z * sc), "f"(v.w * sc)
                 : "memory");
}

// X1 = agg*dinv - X0   (optionally copy X0 into Xt slot)
__global__ void k_x1(const float* __restrict__ X0, int ld0,
                     const float* __restrict__ agg,
                     const float* __restrict__ dinv,
                     float* __restrict__ X1, int ld1,
                     float* __restrict__ X0copy, int ldc,
                     int n) {
    int i = blockIdx.x * blockDim.x + threadIdx.x;
    if (i >= n * 32) return;
    int node = i >> 5;
    int c = (i & 31) * 4;
    float di = __ldg(&dinv[node]);
    float4 x0 = *(const float4*)(X0 + (size_t)node * ld0 + c);
    float4 a  = *(const float4*)(agg + (size_t)node * FDIM + c);
    float4 r;
    r.x = a.x * di - x0.x;
    r.y = a.y * di - x0.y;
    r.z = a.z * di - x0.z;
    r.w = a.w * di - x0.w;
    *(float4*)(X1 + (size_t)node * ld1 + c) = r;
    if (X0copy) *(float4*)(X0copy + (size_t)node * ldc + c) = x0;
}

// X2 = 2*agg*dinv - 2*X1 - X0
__global__ void k_x2(const float* __restrict__ X0, int ld0,
                     const float* __restrict__ X1, int ld1,
                     const float* __restrict__ agg,
                     const float* __restrict__ dinv,
                     float* __restrict__ X2, int ld2,
                     int n) {
    int i = blockIdx.x * blockDim.x + threadIdx.x;
    if (i >= n * 32) return;
    int node = i >> 5;
    int c = (i & 31) * 4;
    float di = 2.0f * __ldg(&dinv[node]);
    float4 x0 = *(const float4*)(X0 + (size_t)node * ld0 + c);
    float4 x1 = *(const float4*)(X1 + (size_t)node * ld1 + c);
    float4 a  = *(const float4*)(agg + (size_t)node * FDIM + c);
    float4 r;
    r.x = a.x * di - 2.0f * x1.x - x0.x;
    r.y = a.y * di - 2.0f * x1.y - x0.y;
    r.z = a.z * di - 2.0f * x1.z - x0.z;
    r.w = a.w * di - 2.0f * x1.w - x0.w;
    *(float4*)(X2 + (size_t)node * ld2 + c) = r;
}

// ============== tf32 mma.sync GEMM: C[128, NT] = A[128,K] @ W[NT,K]^T + epilogue ==============
#define EPI_BIAS     0
#define EPI_RELU_BN  1
#define EPI_RELU_RES 2
#define EPI_RELU     3

__device__ __forceinline__ void mma8(float c[4], const uint32_t a[4], uint32_t b0, uint32_t b1) {
    asm volatile(
        "mma.sync.aligned.m16n8k8.row.col.f32.tf32.tf32.f32 "
        "{%0,%1,%2,%3}, {%4,%5,%6,%7}, {%8,%9}, {%0,%1,%2,%3};"
        : "+f"(c[0]), "+f"(c[1]), "+f"(c[2]), "+f"(c[3])
        : "r"(a[0]), "r"(a[1]), "r"(a[2]), "r"(a[3]), "r"(b0), "r"(b1));
}

// BM=128, BK=32, 256 threads (8 warps), warp tile 32 x (NT/2).
// SMEM layout: As[2][128][36] then Bs[2][NT][36]  (pad 4 -> bank = (4*row + k) % 32, conflict-free)
template<int NT, int EPI>
__global__ void __launch_bounds__(256, 2)
k_gemm_tc(const float* __restrict__ A, int lda, int M, int K,
          const float* __restrict__ W,
          const float* __restrict__ bias,
          const float* __restrict__ gmm, const float* __restrict__ bet,
          const float* __restrict__ mu,  const float* __restrict__ var,
          const float* __restrict__ res, int ldres,
          float* __restrict__ C, int ldc) {
    extern __shared__ float sm[];
    float* const AsBase = sm;                     // 2 * 128 * 36
    float* const BsBase = sm + 2 * 128 * 36;      // 2 * NT  * 36

    const int tid  = threadIdx.x;
    const int wid  = tid >> 5;
    const int lane = tid & 31;
    const int gID  = lane >> 2;     // 0..7
    const int tig  = lane & 3;      // 0..3
    const int m0   = blockIdx.x * 128;

    const int wm = (wid & 3) * 32;          // warp m offset (0,32,64,96)
    const int wn = (wid >> 2) * (NT / 2);   // warp n offset
    constexpr int NTILES = NT / 16;         // n8 tiles per warp

    float c[2][NTILES][4];
    #pragma unroll
    for (int i = 0; i < 2; i++)
        #pragma unroll
        for (int j = 0; j < NTILES; j++)
            #pragma unroll
            for (int q = 0; q < 4; q++) c[i][j][q] = 0.0f;

    const int nch = K >> 5;

    // ---- tile loader: global -> (tf32) -> shared ----
    auto load_tiles = [&](int kt, int buf) {
        float* As = AsBase + buf * (128 * 36);
        float* Bs = BsBase + buf * (NT * 36);
        #pragma unroll
        for (int it = 0; it < 4; it++) {
            int i = tid + it * 256;
            int row = i >> 3, q = i & 7;
            int gm = m0 + row;
            float4 v = make_float4(0.f, 0.f, 0.f, 0.f);
            if (gm < M) v = *(const float4*)(A + (size_t)gm * lda + kt + q * 4);
            uint4 t = make_uint4(f2tf32(v.x), f2tf32(v.y), f2tf32(v.z), f2tf32(v.w));
            *(uint4*)(As + row * 36 + q * 4) = t;
        }
        #pragma unroll
        for (int it = 0; it < NT / 32; it++) {
            int i = tid + it * 256;
            int row = i >> 3, q = i & 7;
            float4 v = *(const float4*)(W + (size_t)row * K + kt + q * 4);
            uint4 t = make_uint4(f2tf32(v.x), f2tf32(v.y), f2tf32(v.z), f2tf32(v.w));
            *(uint4*)(Bs + row * 36 + q * 4) = t;
        }
    };

    load_tiles(0, 0);
    __syncthreads();

    for (int ch = 0; ch < nch; ch++) {
        const int buf = ch & 1;
        if (ch + 1 < nch) load_tiles((ch + 1) << 5, buf ^ 1);

        const float* As = AsBase + buf * (128 * 36);
        const float* Bs = BsBase + buf * (NT * 36);

        #pragma unroll
        for (int ks = 0; ks < 32; ks += 8) {
            uint32_t a[2][4];
            #pragma unroll
            for (int mt = 0; mt < 2; mt++) {
                const int r = wm + mt * 16 + gID;
                a[mt][0] = __float_as_uint(As[r * 36 + ks + tig]);
                a[mt][1] = __float_as_uint(As[(r + 8) * 36 + ks + tig]);
                a[mt][2] = __float_as_uint(As[r * 36 + ks + tig + 4]);
                a[mt][3] = __float_as_uint(As[(r + 8) * 36 + ks + tig + 4]);
            }
            #pragma unroll
            for (int nt = 0; nt < NTILES; nt++) {
                const int nr = wn + nt * 8 + gID;
                uint32_t b0 = __float_as_uint(Bs[nr * 36 + ks + tig]);
                uint32_t b1 = __float_as_uint(Bs[nr * 36 + ks + tig + 4]);
                mma8(c[0][nt], a[0], b0, b1);
                mma8(c[1][nt], a[1], b0, b1);
            }
        }
        __syncthreads();
    }

    // ---- epilogue ----
    #pragma unroll
    for (int mt = 0; mt < 2; mt++) {
        #pragma unroll
        for (int nt = 0; nt < NTILES; nt++) {
            const int col = wn + nt * 8 + tig * 2;
            #pragma unroll
            for (int half = 0; half < 2; half++) {
                const int m = m0 + wm + mt * 16 + gID + half * 8;
                if (m >= M) continue;
                float v0 = c[mt][nt][half * 2 + 0];
                float v1 = c[mt][nt][half * 2 + 1];
                v0 += __ldg(&bias[col]);
                v1 += __ldg(&bias[col + 1]);
                if (EPI == EPI_RELU_BN) {
                    v0 = fmaxf(v0, 0.0f);
                    v1 = fmaxf(v1, 0.0f);
                    v0 = (v0 - __ldg(&mu[col]))     * rsqrtf(__ldg(&var[col])     + 1e-5f) * __ldg(&gmm[col])     + __ldg(&bet[col]);
                    v1 = (v1 - __ldg(&mu[col + 1])) * rsqrtf(__ldg(&var[col + 1]) + 1e-5f) * __ldg(&gmm[col + 1]) + __ldg(&bet[col + 1]);
                } else if (EPI == EPI_RELU_RES) {
                    float2 rr = *(const float2*)(res + (size_t)m * ldres + col);
                    v0 = fmaxf(v0, 0.0f) + rr.x;
                    v1 = fmaxf(v1, 0.0f) + rr.y;
                } else if (EPI == EPI_RELU) {
                    v0 = fmaxf(v0, 0.0f);
                    v1 = fmaxf(v1, 0.0f);
                }
                *(float2*)(C + (size_t)m * ldc + col) = make_float2(v0, v1);
            }
        }
    }
}

// ======================= launch =======================
extern "C" void kernel_launch(void* const* d_in, const int* in_sizes, int n_in,
                              void* d_out, int out_size) {
    const float* feat  = (const float*)d_in[0];
    const int*   esrc  = (const int*)d_in[1];
    const int*   edst  = (const int*)d_in[2];
    const float* W1    = (const float*)d_in[3];
    const float* b1    = (const float*)d_in[4];
    const float* gamma = (const float*)d_in[5];
    const float* beta  = (const float*)d_in[6];
    const float* mean  = (const float*)d_in[7];
    const float* var   = (const float*)d_in[8];
    const float* W3    = (const float*)d_in[9];
    const float* b3    = (const float*)d_in[10];
    const float* Wm1   = (const float*)d_in[11];
    const float* bm1   = (const float*)d_in[12];
    const float* Wm2   = (const float*)d_in[13];
    const float* bm2   = (const float*)d_in[14];

    const int n  = in_sizes[0] / FDIM;
    const int ne = in_sizes[1];

    float *dinv, *agg, *xt1, *xt2, *m1, *m2;
    cudaGetSymbolAddress((void**)&dinv, g_dinv);
    cudaGetSymbolAddress((void**)&agg,  g_agg);
    cudaGetSymbolAddress((void**)&xt1,  g_xt1);
    cudaGetSymbolAddress((void**)&xt2,  g_xt2);
    cudaGetSymbolAddress((void**)&m1,   g_m1);
    cudaGetSymbolAddress((void**)&m2,   g_m2);

    const size_t aggBytes = (size_t)n * FDIM * sizeof(float);
    const int egrid = (ne + 7) / 8;
    const int vgrid = (n * 32 + 255) / 256;
    const int ggrid = (n + 127) / 128;

    const int SMEM_N128 = (2 * 128 * 36 + 2 * 128 * 36) * 4;  // 73728
    const int SMEM_N64  = (2 * 128 * 36 + 2 * 64  * 36) * 4;  // 55296
    cudaFuncSetAttribute(k_gemm_tc<128, EPI_RELU_BN>,  cudaFuncAttributeMaxDynamicSharedMemorySize, SMEM_N128);
    cudaFuncSetAttribute(k_gemm_tc<128, EPI_RELU_RES>, cudaFuncAttributeMaxDynamicSharedMemorySize, SMEM_N128);
    cudaFuncSetAttribute(k_gemm_tc<128, EPI_RELU>,     cudaFuncAttributeMaxDynamicSharedMemorySize, SMEM_N128);
    cudaFuncSetAttribute(k_gemm_tc<64,  EPI_BIAS>,     cudaFuncAttributeMaxDynamicSharedMemorySize, SMEM_N64);

    // degrees -> dinv
    cudaMemsetAsync(dinv, 0, (size_t)n * sizeof(float));
    k_deg<<<(ne + 255) / 256, 256>>>(edst, ne, dinv);
    k_dinv<<<(n + 255) / 256, 256>>>(dinv, n);

    // ---- Cheb layer 1 (X0 = features) ----
    cudaMemsetAsync(agg, 0, aggBytes);
    k_scatter<<<egrid, 256>>>(feat, FDIM, esrc, edst, dinv, agg, ne);
    k_x1<<<vgrid, 256>>>(feat, FDIM, agg, dinv, xt1 + 128, 384, xt1, 384, n);
    cudaMemsetAsync(agg, 0, aggBytes);
    k_scatter<<<egrid, 256>>>(xt1 + 128, 384, esrc, edst, dinv, agg, ne);
    k_x2<<<vgrid, 256>>>(xt1, 384, xt1 + 128, 384, agg, dinv, xt1 + 256, 384, n);
    // y = BN(relu(Xt1 @ W1^T + b1)) -> xt2[:, 0:128] (also the residual)
    k_gemm_tc<128, EPI_RELU_BN><<<ggrid, 256, SMEM_N128>>>(xt1, 384, n, 384, W1, b1,
                                                           gamma, beta, mean, var,
                                                           (const float*)nullptr, 0, xt2, 384);

    // ---- Cheb layer 2 (X0 = xt2[:, 0:128]) ----
    cudaMemsetAsync(agg, 0, aggBytes);
    k_scatter<<<egrid, 256>>>(xt2, 384, esrc, edst, dinv, agg, ne);
    k_x1<<<vgrid, 256>>>(xt2, 384, agg, dinv, xt2 + 128, 384, (float*)nullptr, 0, n);
    cudaMemsetAsync(agg, 0, aggBytes);
    k_scatter<<<egrid, 256>>>(xt2 + 128, 384, esrc, edst, dinv, agg, ne);
    k_x2<<<vgrid, 256>>>(xt2, 384, xt2 + 128, 384, agg, dinv, xt2 + 256, 384, n);
    // x = relu(Xt2 @ W3^T + b3) + residual -> m1
    k_gemm_tc<128, EPI_RELU_RES><<<ggrid, 256, SMEM_N128>>>(xt2, 384, n, 384, W3, b3,
                                                            (const float*)nullptr, (const float*)nullptr,
                                                            (const float*)nullptr, (const float*)nullptr,
                                                            xt2, 384, m1, 128);

    // ---- MLP head ----
    k_gemm_tc<128, EPI_RELU><<<ggrid, 256, SMEM_N128>>>(m1, 128, n, 128, Wm1, bm1,
                                                        (const float*)nullptr, (const float*)nullptr,
                                                        (const float*)nullptr, (const float*)nullptr,
                                                        (const float*)nullptr, 0, m2, 128);
    k_gemm_tc<64, EPI_BIAS><<<ggrid, 256, SMEM_N64>>>(m2, 128, n, 128, Wm2, bm2,
                                                      (const float*)nullptr, (const float*)nullptr,
                                                      (const float*)nullptr, (const float*)nullptr,
                                                      (const float*)nullptr, 0, (float*)d_out, 64);
}

// round 7
// speedup vs baseline: 2.6338x; 1.5450x over previous
#include <cuda_runtime.h>
#include <cstdint>
#include <cstddef>

#define NMAX 100000
#define NEMAX 600000
#define FDIM 128

// ---- static device scratch (no allocations allowed) ----
__device__ int   g_deg[NMAX];
__device__ int   g_off[NMAX + 1];
__device__ int   g_pos[NMAX];
__device__ int   g_blk[256];
__device__ int   g_csrc[NEMAX];
__device__ float g_dinv[NMAX];
__device__ float g_xt1[NMAX * 384];
__device__ float g_xt2[NMAX * 384];
__device__ float g_m1[NMAX * FDIM];
__device__ float g_m2[NMAX * FDIM];

__device__ __forceinline__ uint32_t f2tf32(float x) {
    uint32_t r;
    asm("cvt.rna.tf32.f32 %0, %1;" : "=r"(r) : "f"(x));
    return r;
}

// ======================= CSR build =======================
__global__ void k_degi(const int* __restrict__ dst, int ne, int* __restrict__ deg) {
    int i = blockIdx.x * blockDim.x + threadIdx.x;
    if (i < ne) atomicAdd(&deg[dst[i]], 1);
}

__global__ void k_dinvi(const int* __restrict__ deg, float* __restrict__ dinv, int n) {
    int i = blockIdx.x * blockDim.x + threadIdx.x;
    if (i < n) {
        int d = deg[i];
        dinv[i] = 1.0f / sqrtf((float)(d > 1 ? d : 1));
    }
}

__global__ void k_scan1(const int* __restrict__ deg, int n,
                        int* __restrict__ excl, int* __restrict__ blk) {
    __shared__ int sh[512];
    int tid = threadIdx.x;
    int i = blockIdx.x * 512 + tid;
    int v = (i < n) ? deg[i] : 0;
    sh[tid] = v;
    __syncthreads();
    #pragma unroll
    for (int ofs = 1; ofs < 512; ofs <<= 1) {
        int t = (tid >= ofs) ? sh[tid - ofs] : 0;
        __syncthreads();
        sh[tid] += t;
        __syncthreads();
    }
    if (i < n) excl[i] = sh[tid] - v;
    if (tid == 511) blk[blockIdx.x] = sh[511];
}

__global__ void k_scan2(int* __restrict__ blk, int nb, int* __restrict__ off_n) {
    if (threadIdx.x == 0 && blockIdx.x == 0) {
        int acc = 0;
        for (int b = 0; b < nb; b++) { int t = blk[b]; blk[b] = acc; acc += t; }
        *off_n = acc;
    }
}

__global__ void k_scan3(int* __restrict__ off, int* __restrict__ pos,
                        const int* __restrict__ blk, int n) {
    int i = blockIdx.x * 512 + threadIdx.x;
    if (i < n) {
        int o = off[i] + blk[blockIdx.x];
        off[i] = o;
        pos[i] = o;
    }
}

__global__ void k_bucket(const int* __restrict__ src, const int* __restrict__ dst, int ne,
                         int* __restrict__ pos, int* __restrict__ csrc) {
    int e = blockIdx.x * blockDim.x + threadIdx.x;
    if (e < ne) {
        int p = atomicAdd(&pos[dst[e]], 1);
        csrc[p] = src[e];
    }
}

// ======================= fused Laplacian aggregation =======================
// MODE 0:  Xout = (sum X[s]*dinv[s]) * dinv[v] - X0[v]          (+optional X0 copy)
// MODE 1:  Xout = 2*(sum X1[s]*dinv[s])*dinv[v] - 2*X1[v] - X0[v]
template<int MODE>
__global__ void __launch_bounds__(256)
k_agg(const float* __restrict__ Xin, int ldin,
      const float* __restrict__ X0, int ld0,
      const float* __restrict__ X1, int ld1,
      const float* __restrict__ dinv,
      const int* __restrict__ off, const int* __restrict__ csrc,
      float* __restrict__ Xout, int ldo,
      float* __restrict__ X0copy, int ldc, int n) {
    int v = blockIdx.x * 8 + (threadIdx.x >> 5);
    if (v >= n) return;
    int lane = threadIdx.x & 31;
    int beg = __ldg(&off[v]);
    int end = __ldg(&off[v + 1]);

    float4 acc = make_float4(0.f, 0.f, 0.f, 0.f);
    for (int j = beg; j < end; j++) {
        int s = __ldg(&csrc[j]);
        float sc = __ldg(&dinv[s]);
        float4 x = *(const float4*)(Xin + (size_t)s * ldin + lane * 4);
        acc.x += x.x * sc;
        acc.y += x.y * sc;
        acc.z += x.z * sc;
        acc.w += x.w * sc;
    }
    float dv = __ldg(&dinv[v]);
    float4 x0 = *(const float4*)(X0 + (size_t)v * ld0 + lane * 4);
    float4 r;
    if (MODE == 0) {
        r.x = acc.x * dv - x0.x;
        r.y = acc.y * dv - x0.y;
        r.z = acc.z * dv - x0.z;
        r.w = acc.w * dv - x0.w;
        if (X0copy) *(float4*)(X0copy + (size_t)v * ldc + lane * 4) = x0;
    } else {
        float d2 = 2.0f * dv;
        float4 x1 = *(const float4*)(X1 + (size_t)v * ld1 + lane * 4);
        r.x = acc.x * d2 - 2.0f * x1.x - x0.x;
        r.y = acc.y * d2 - 2.0f * x1.y - x0.y;
        r.z = acc.z * d2 - 2.0f * x1.z - x0.z;
        r.w = acc.w * d2 - 2.0f * x1.w - x0.w;
    }
    *(float4*)(Xout + (size_t)v * ldo + lane * 4) = r;
}

// ============== tf32 mma.sync GEMM: C[128, NT] = A[128,K] @ W[NT,K]^T + epilogue ==============
#define EPI_BIAS     0
#define EPI_RELU_BN  1
#define EPI_RELU_RES 2
#define EPI_RELU     3

__device__ __forceinline__ void mma8(float c[4], const uint32_t a[4], uint32_t b0, uint32_t b1) {
    asm volatile(
        "mma.sync.aligned.m16n8k8.row.col.f32.tf32.tf32.f32 "
        "{%0,%1,%2,%3}, {%4,%5,%6,%7}, {%8,%9}, {%0,%1,%2,%3};"
        : "+f"(c[0]), "+f"(c[1]), "+f"(c[2]), "+f"(c[3])
        : "r"(a[0]), "r"(a[1]), "r"(a[2]), "r"(a[3]), "r"(b0), "r"(b1));
}

template<int NT, int EPI>
__global__ void __launch_bounds__(256, 2)
k_gemm_tc(const float* __restrict__ A, int lda, int M, int K,
          const float* __restrict__ W,
          const float* __restrict__ bias,
          const float* __restrict__ gmm, const float* __restrict__ bet,
          const float* __restrict__ mu,  const float* __restrict__ var,
          const float* __restrict__ res, int ldres,
          float* __restrict__ C, int ldc) {
    extern __shared__ float sm[];
    float* const AsBase = sm;
    float* const BsBase = sm + 2 * 128 * 36;

    const int tid  = threadIdx.x;
    const int wid  = tid >> 5;
    const int lane = tid & 31;
    const int gID  = lane >> 2;
    const int tig  = lane & 3;
    const int m0   = blockIdx.x * 128;

    const int wm = (wid & 3) * 32;
    const int wn = (wid >> 2) * (NT / 2);
    constexpr int NTILES = NT / 16;

    float c[2][NTILES][4];
    #pragma unroll
    for (int i = 0; i < 2; i++)
        #pragma unroll
        for (int j = 0; j < NTILES; j++)
            #pragma unroll
            for (int q = 0; q < 4; q++) c[i][j][q] = 0.0f;

    const int nch = K >> 5;

    auto load_tiles = [&](int kt, int buf) {
        float* As = AsBase + buf * (128 * 36);
        float* Bs = BsBase + buf * (NT * 36);
        #pragma unroll
        for (int it = 0; it < 4; it++) {
            int i = tid + it * 256;
            int row = i >> 3, q = i & 7;
            int gm = m0 + row;
            float4 v = make_float4(0.f, 0.f, 0.f, 0.f);
            if (gm < M) v = *(const float4*)(A + (size_t)gm * lda + kt + q * 4);
            uint4 t = make_uint4(f2tf32(v.x), f2tf32(v.y), f2tf32(v.z), f2tf32(v.w));
            *(uint4*)(As + row * 36 + q * 4) = t;
        }
        #pragma unroll
        for (int it = 0; it < NT / 32; it++) {
            int i = tid + it * 256;
            int row = i >> 3, q = i & 7;
            float4 v = *(const float4*)(W + (size_t)row * K + kt + q * 4);
            uint4 t = make_uint4(f2tf32(v.x), f2tf32(v.y), f2tf32(v.z), f2tf32(v.w));
            *(uint4*)(Bs + row * 36 + q * 4) = t;
        }
    };

    load_tiles(0, 0);
    __syncthreads();

    for (int ch = 0; ch < nch; ch++) {
        const int buf = ch & 1;
        if (ch + 1 < nch) load_tiles((ch + 1) << 5, buf ^ 1);

        const float* As = AsBase + buf * (128 * 36);
        const float* Bs = BsBase + buf * (NT * 36);

        #pragma unroll
        for (int ks = 0; ks < 32; ks += 8) {
            uint32_t a[2][4];
            #pragma unroll
            for (int mt = 0; mt < 2; mt++) {
                const int r = wm + mt * 16 + gID;
                a[mt][0] = __float_as_uint(As[r * 36 + ks + tig]);
                a[mt][1] = __float_as_uint(As[(r + 8) * 36 + ks + tig]);
                a[mt][2] = __float_as_uint(As[r * 36 + ks + tig + 4]);
                a[mt][3] = __float_as_uint(As[(r + 8) * 36 + ks + tig + 4]);
            }
            #pragma unroll
            for (int nt = 0; nt < NTILES; nt++) {
                const int nr = wn + nt * 8 + gID;
                uint32_t b0 = __float_as_uint(Bs[nr * 36 + ks + tig]);
                uint32_t b1 = __float_as_uint(Bs[nr * 36 + ks + tig + 4]);
                mma8(c[0][nt], a[0], b0, b1);
                mma8(c[1][nt], a[1], b0, b1);
            }
        }
        __syncthreads();
    }

    #pragma unroll
    for (int mt = 0; mt < 2; mt++) {
        #pragma unroll
        for (int nt = 0; nt < NTILES; nt++) {
            const int col = wn + nt * 8 + tig * 2;
            #pragma unroll
            for (int half = 0; half < 2; half++) {
                const int m = m0 + wm + mt * 16 + gID + half * 8;
                if (m >= M) continue;
                float v0 = c[mt][nt][half * 2 + 0];
                float v1 = c[mt][nt][half * 2 + 1];
                v0 += __ldg(&bias[col]);
                v1 += __ldg(&bias[col + 1]);
                if (EPI == EPI_RELU_BN) {
                    v0 = fmaxf(v0, 0.0f);
                    v1 = fmaxf(v1, 0.0f);
                    v0 = (v0 - __ldg(&mu[col]))     * rsqrtf(__ldg(&var[col])     + 1e-5f) * __ldg(&gmm[col])     + __ldg(&bet[col]);
                    v1 = (v1 - __ldg(&mu[col + 1])) * rsqrtf(__ldg(&var[col + 1]) + 1e-5f) * __ldg(&gmm[col + 1]) + __ldg(&bet[col + 1]);
                } else if (EPI == EPI_RELU_RES) {
                    float2 rr = *(const float2*)(res + (size_t)m * ldres + col);
                    v0 = fmaxf(v0, 0.0f) + rr.x;
                    v1 = fmaxf(v1, 0.0f) + rr.y;
                } else if (EPI == EPI_RELU) {
                    v0 = fmaxf(v0, 0.0f);
                    v1 = fmaxf(v1, 0.0f);
                }
                *(float2*)(C + (size_t)m * ldc + col) = make_float2(v0, v1);
            }
        }
    }
}

// ======================= launch =======================
extern "C" void kernel_launch(void* const* d_in, const int* in_sizes, int n_in,
                              void* d_out, int out_size) {
    const float* feat  = (const float*)d_in[0];
    const int*   esrc  = (const int*)d_in[1];
    const int*   edst  = (const int*)d_in[2];
    const float* W1    = (const float*)d_in[3];
    const float* b1    = (const float*)d_in[4];
    const float* gamma = (const float*)d_in[5];
    const float* beta  = (const float*)d_in[6];
    const float* mean  = (const float*)d_in[7];
    const float* var   = (const float*)d_in[8];
    const float* W3    = (const float*)d_in[9];
    const float* b3    = (const float*)d_in[10];
    const float* Wm1   = (const float*)d_in[11];
    const float* bm1   = (const float*)d_in[12];
    const float* Wm2   = (const float*)d_in[13];
    const float* bm2   = (const float*)d_in[14];

    const int n  = in_sizes[0] / FDIM;
    const int ne = in_sizes[1];

    int *deg, *off, *pos, *blk, *csrc;
    float *dinv, *xt1, *xt2, *m1, *m2;
    cudaGetSymbolAddress((void**)&deg,  g_deg);
    cudaGetSymbolAddress((void**)&off,  g_off);
    cudaGetSymbolAddress((void**)&pos,  g_pos);
    cudaGetSymbolAddress((void**)&blk,  g_blk);
    cudaGetSymbolAddress((void**)&csrc, g_csrc);
    cudaGetSymbolAddress((void**)&dinv, g_dinv);
    cudaGetSymbolAddress((void**)&xt1,  g_xt1);
    cudaGetSymbolAddress((void**)&xt2,  g_xt2);
    cudaGetSymbolAddress((void**)&m1,   g_m1);
    cudaGetSymbolAddress((void**)&m2,   g_m2);

    const int nb    = (n + 511) / 512;
    const int agrid = (n + 7) / 8;        // warp per node
    const int ggrid = (n + 127) / 128;

    const int SMEM_N128 = (2 * 128 * 36 + 2 * 128 * 36) * 4;
    const int SMEM_N64  = (2 * 128 * 36 + 2 * 64  * 36) * 4;
    cudaFuncSetAttribute(k_gemm_tc<128, EPI_RELU_BN>,  cudaFuncAttributeMaxDynamicSharedMemorySize, SMEM_N128);
    cudaFuncSetAttribute(k_gemm_tc<128, EPI_RELU_RES>, cudaFuncAttributeMaxDynamicSharedMemorySize, SMEM_N128);
    cudaFuncSetAttribute(k_gemm_tc<128, EPI_RELU>,     cudaFuncAttributeMaxDynamicSharedMemorySize, SMEM_N128);
    cudaFuncSetAttribute(k_gemm_tc<64,  EPI_BIAS>,     cudaFuncAttributeMaxDynamicSharedMemorySize, SMEM_N64);

    // ---- CSR build ----
    cudaMemsetAsync(deg, 0, (size_t)n * sizeof(int));
    k_degi<<<(ne + 255) / 256, 256>>>(edst, ne, deg);
    k_dinvi<<<(n + 255) / 256, 256>>>(deg, dinv, n);
    k_scan1<<<nb, 512>>>(deg, n, off, blk);
    k_scan2<<<1, 32>>>(blk, nb, off + n);
    k_scan3<<<nb, 512>>>(off, pos, blk, n);
    k_bucket<<<(ne + 255) / 256, 256>>>(esrc, edst, ne, pos, csrc);

    // ---- Cheb layer 1 (X0 = features) ----
    k_agg<0><<<agrid, 256>>>(feat, FDIM, feat, FDIM, (const float*)nullptr, 0,
                             dinv, off, csrc, xt1 + 128, 384, xt1, 384, n);
    k_agg<1><<<agrid, 256>>>(xt1 + 128, 384, xt1, 384, xt1 + 128, 384,
                             dinv, off, csrc, xt1 + 256, 384, (float*)nullptr, 0, n);
    k_gemm_tc<128, EPI_RELU_BN><<<ggrid, 256, SMEM_N128>>>(xt1, 384, n, 384, W1, b1,
                                                           gamma, beta, mean, var,
                                                           (const float*)nullptr, 0, xt2, 384);

    // ---- Cheb layer 2 (X0 = xt2[:, 0:128]) ----
    k_agg<0><<<agrid, 256>>>(xt2, 384, xt2, 384, (const float*)nullptr, 0,
                             dinv, off, csrc, xt2 + 128, 384, (float*)nullptr, 0, n);
    k_agg<1><<<agrid, 256>>>(xt2 + 128, 384, xt2, 384, xt2 + 128, 384,
                             dinv, off, csrc, xt2 + 256, 384, (float*)nullptr, 0, n);
    k_gemm_tc<128, EPI_RELU_RES><<<ggrid, 256, SMEM_N128>>>(xt2, 384, n, 384, W3, b3,
                                                            (const float*)nullptr, (const float*)nullptr,
                                                            (const float*)nullptr, (const float*)nullptr,
                                                            xt2, 384, m1, 128);

    // ---- MLP head ----
    k_gemm_tc<128, EPI_RELU><<<ggrid, 256, SMEM_N128>>>(m1, 128, n, 128, Wm1, bm1,
                                                        (const float*)nullptr, (const float*)nullptr,
                                                        (const float*)nullptr, (const float*)nullptr,
                                                        (const float*)nullptr, 0, m2, 128);
    k_gemm_tc<64, EPI_BIAS><<<ggrid, 256, SMEM_N64>>>(m2, 128, n, 128, Wm2, bm2,
                                                      (const float*)nullptr, (const float*)nullptr,
                                                      (const float*)nullptr, (const float*)nullptr,
                                                      (const float*)nullptr, 0, (float*)d_out, 64);
}

// round 8
// speedup vs baseline: 2.7896x; 1.0592x over previous
#include <cuda_runtime.h>
#include <cstdint>
#include <cstddef>

#define NMAX 100000
#define NEMAX 600000
#define FDIM 128

// ---- static device scratch (no allocations allowed) ----
__device__ int   g_deg[NMAX];
__device__ int   g_off[NMAX + 1];
__device__ int   g_pos[NMAX];
__device__ int   g_blk[256];
__device__ int   g_csrc[NEMAX];
__device__ float g_dinv[NMAX];
__device__ float g_b0[NMAX * FDIM];   // y (layer1 out / residual)
__device__ float g_b1[NMAX * FDIM];   // G0 / later reuse
__device__ float g_b2[NMAX * FDIM];   // G1
__device__ float g_b3[NMAX * FDIM];   // m1
__device__ float g_w1t[128 * 384];
__device__ float g_w3t[128 * 384];

__device__ __forceinline__ uint32_t f2tf32(float x) {
    uint32_t r;
    asm("cvt.rna.tf32.f32 %0, %1;" : "=r"(r) : "f"(x));
    return r;
}

// ======================= CSR build =======================
__global__ void k_degi(const int* __restrict__ dst, int ne, int* __restrict__ deg) {
    int i = blockIdx.x * blockDim.x + threadIdx.x;
    if (i < ne) atomicAdd(&deg[dst[i]], 1);
}

__global__ void k_dinvi(const int* __restrict__ deg, float* __restrict__ dinv, int n) {
    int i = blockIdx.x * blockDim.x + threadIdx.x;
    if (i < n) {
        int d = deg[i];
        dinv[i] = 1.0f / sqrtf((float)(d > 1 ? d : 1));
    }
}

__global__ void k_scan1(const int* __restrict__ deg, int n,
                        int* __restrict__ excl, int* __restrict__ blk) {
    __shared__ int sh[512];
    int tid = threadIdx.x;
    int i = blockIdx.x * 512 + tid;
    int v = (i < n) ? deg[i] : 0;
    sh[tid] = v;
    __syncthreads();
    #pragma unroll
    for (int ofs = 1; ofs < 512; ofs <<= 1) {
        int t = (tid >= ofs) ? sh[tid - ofs] : 0;
        __syncthreads();
        sh[tid] += t;
        __syncthreads();
    }
    if (i < n) excl[i] = sh[tid] - v;
    if (tid == 511) blk[blockIdx.x] = sh[511];
}

// parallel exclusive scan of block totals (nb <= 256)
__global__ void k_scan2p(int* __restrict__ blk, int nb, int* __restrict__ off_n) {
    __shared__ int sh[256];
    int tid = threadIdx.x;
    int v = (tid < nb) ? blk[tid] : 0;
    sh[tid] = v;
    __syncthreads();
    #pragma unroll
    for (int ofs = 1; ofs < 256; ofs <<= 1) {
        int t = (tid >= ofs) ? sh[tid - ofs] : 0;
        __syncthreads();
        sh[tid] += t;
        __syncthreads();
    }
    if (tid < nb) blk[tid] = sh[tid] - v;
    if (tid == 255) *off_n = sh[255];
}

__global__ void k_scan3(int* __restrict__ off, int* __restrict__ pos,
                        const int* __restrict__ blk, int n) {
    int i = blockIdx.x * 512 + threadIdx.x;
    if (i < n) {
        int o = off[i] + blk[blockIdx.x];
        off[i] = o;
        pos[i] = o;
    }
}

__global__ void k_bucket(const int* __restrict__ src, const int* __restrict__ dst, int ne,
                         int* __restrict__ pos, int* __restrict__ csrc) {
    int e = blockIdx.x * blockDim.x + threadIdx.x;
    if (e < ne) {
        int p = atomicAdd(&pos[dst[e]], 1);
        csrc[p] = src[e];
    }
}

// ======================= weight transform =======================
// W [128,384] = [W0|W1|W2] -> W' = [W0-W1+W2 | W1-4W2 | 2W2]
__global__ void k_wt(const float* __restrict__ W, float* __restrict__ Wt) {
    int i = blockIdx.x * blockDim.x + threadIdx.x;
    if (i >= 128 * 128) return;
    int o = i >> 7, k = i & 127;
    float w0 = W[o * 384 + k];
    float w1 = W[o * 384 + 128 + k];
    float w2 = W[o * 384 + 256 + k];
    Wt[o * 384 + k]       = w0 - w1 + w2;
    Wt[o * 384 + 128 + k] = w1 - 4.0f * w2;
    Wt[o * 384 + 256 + k] = 2.0f * w2;
}

// ======================= pure A_hat application =======================
// Xout[v] = (sum_{s in N(v)} Xin[s]*dinv[s]) * dinv[v]     (ld = 128 everywhere)
__global__ void __launch_bounds__(256)
k_ahat(const float* __restrict__ Xin,
       const float* __restrict__ dinv,
       const int* __restrict__ off, const int* __restrict__ csrc,
       float* __restrict__ Xout, int n) {
    int v = blockIdx.x * 8 + (threadIdx.x >> 5);
    if (v >= n) return;
    int lane = threadIdx.x & 31;
    int beg = __ldg(&off[v]);
    int end = __ldg(&off[v + 1]);

    float4 acc = make_float4(0.f, 0.f, 0.f, 0.f);
    int j = beg;
    // 2-way unrolled with prefetched indices to raise MLP
    for (; j + 2 <= end; j += 2) {
        int s0 = __ldg(&csrc[j]);
        int s1 = __ldg(&csrc[j + 1]);
        float c0 = __ldg(&dinv[s0]);
        float c1 = __ldg(&dinv[s1]);
        float4 x0 = *(const float4*)(Xin + (size_t)s0 * FDIM + lane * 4);
        float4 x1 = *(const float4*)(Xin + (size_t)s1 * FDIM + lane * 4);
        acc.x += x0.x * c0 + x1.x * c1;
        acc.y += x0.y * c0 + x1.y * c1;
        acc.z += x0.z * c0 + x1.z * c1;
        acc.w += x0.w * c0 + x1.w * c1;
    }
    if (j < end) {
        int s = __ldg(&csrc[j]);
        float c = __ldg(&dinv[s]);
        float4 x = *(const float4*)(Xin + (size_t)s * FDIM + lane * 4);
        acc.x += x.x * c;
        acc.y += x.y * c;
        acc.z += x.z * c;
        acc.w += x.w * c;
    }
    float dv = __ldg(&dinv[v]);
    float4 r = make_float4(acc.x * dv, acc.y * dv, acc.z * dv, acc.w * dv);
    *(float4*)(Xout + (size_t)v * FDIM + lane * 4) = r;
}

// ============== tf32 mma.sync GEMM: C[128, NT] = [A0|A1|A2][128,K] @ W[NT,K]^T + epilogue ==============
#define EPI_BIAS     0
#define EPI_RELU_BN  1
#define EPI_RELU_RES 2
#define EPI_RELU     3

__device__ __forceinline__ void mma8(float c[4], const uint32_t a[4], uint32_t b0, uint32_t b1) {
    asm volatile(
        "mma.sync.aligned.m16n8k8.row.col.f32.tf32.tf32.f32 "
        "{%0,%1,%2,%3}, {%4,%5,%6,%7}, {%8,%9}, {%0,%1,%2,%3};"
        : "+f"(c[0]), "+f"(c[1]), "+f"(c[2]), "+f"(c[3])
        : "r"(a[0]), "r"(a[1]), "r"(a[2]), "r"(a[3]), "r"(b0), "r"(b1));
}

// A operand split into up to 3 arrays of 128 cols each (ld = 128); chunk kt picks the array.
template<int NT, int EPI>
__global__ void __launch_bounds__(256, 2)
k_gemm_tc(const float* __restrict__ A0, const float* __restrict__ A1, const float* __restrict__ A2,
          int M, int K,
          const float* __restrict__ W,
          const float* __restrict__ bias,
          const float* __restrict__ gmm, const float* __restrict__ bet,
          const float* __restrict__ mu,  const float* __restrict__ var,
          const float* __restrict__ res,
          float* __restrict__ C, int ldc) {
    extern __shared__ float sm[];
    float* const AsBase = sm;
    float* const BsBase = sm + 2 * 128 * 36;

    const int tid  = threadIdx.x;
    const int wid  = tid >> 5;
    const int lane = tid & 31;
    const int gID  = lane >> 2;
    const int tig  = lane & 3;
    const int m0   = blockIdx.x * 128;

    const int wm = (wid & 3) * 32;
    const int wn = (wid >> 2) * (NT / 2);
    constexpr int NTILES = NT / 16;

    float c[2][NTILES][4];
    #pragma unroll
    for (int i = 0; i < 2; i++)
        #pragma unroll
        for (int j = 0; j < NTILES; j++)
            #pragma unroll
            for (int q = 0; q < 4; q++) c[i][j][q] = 0.0f;

    const int nch = K >> 5;

    auto load_tiles = [&](int kt, int buf) {
        const float* Ap = (kt < 128) ? A0 : ((kt < 256) ? A1 : A2);
        const int kk = kt & 127;
        float* As = AsBase + buf * (128 * 36);
        float* Bs = BsBase + buf * (NT * 36);
        #pragma unroll
        for (int it = 0; it < 4; it++) {
            int i = tid + it * 256;
            int row = i >> 3, q = i & 7;
            int gm = m0 + row;
            float4 v = make_float4(0.f, 0.f, 0.f, 0.f);
            if (gm < M) v = *(const float4*)(Ap + (size_t)gm * FDIM + kk + q * 4);
            uint4 t = make_uint4(f2tf32(v.x), f2tf32(v.y), f2tf32(v.z), f2tf32(v.w));
            *(uint4*)(As + row * 36 + q * 4) = t;
        }
        #pragma unroll
        for (int it = 0; it < NT / 32; it++) {
            int i = tid + it * 256;
            int row = i >> 3, q = i & 7;
            float4 v = *(const float4*)(W + (size_t)row * K + kt + q * 4);
            uint4 t = make_uint4(f2tf32(v.x), f2tf32(v.y), f2tf32(v.z), f2tf32(v.w));
            *(uint4*)(Bs + row * 36 + q * 4) = t;
        }
    };

    load_tiles(0, 0);
    __syncthreads();

    for (int ch = 0; ch < nch; ch++) {
        const int buf = ch & 1;
        if (ch + 1 < nch) load_tiles((ch + 1) << 5, buf ^ 1);

        const float* As = AsBase + buf * (128 * 36);
        const float* Bs = BsBase + buf * (NT * 36);

        #pragma unroll
        for (int ks = 0; ks < 32; ks += 8) {
            uint32_t a[2][4];
            #pragma unroll
            for (int mt = 0; mt < 2; mt++) {
                const int r = wm + mt * 16 + gID;
                a[mt][0] = __float_as_uint(As[r * 36 + ks + tig]);
                a[mt][1] = __float_as_uint(As[(r + 8) * 36 + ks + tig]);
                a[mt][2] = __float_as_uint(As[r * 36 + ks + tig + 4]);
                a[mt][3] = __float_as_uint(As[(r + 8) * 36 + ks + tig + 4]);
            }
            #pragma unroll
            for (int nt = 0; nt < NTILES; nt++) {
                const int nr = wn + nt * 8 + gID;
                uint32_t b0 = __float_as_uint(Bs[nr * 36 + ks + tig]);
                uint32_t b1 = __float_as_uint(Bs[nr * 36 + ks + tig + 4]);
                mma8(c[0][nt], a[0], b0, b1);
                mma8(c[1][nt], a[1], b0, b1);
            }
        }
        __syncthreads();
    }

    #pragma unroll
    for (int mt = 0; mt < 2; mt++) {
        #pragma unroll
        for (int nt = 0; nt < NTILES; nt++) {
            const int col = wn + nt * 8 + tig * 2;
            #pragma unroll
            for (int half = 0; half < 2; half++) {
                const int m = m0 + wm + mt * 16 + gID + half * 8;
                if (m >= M) continue;
                float v0 = c[mt][nt][half * 2 + 0];
                float v1 = c[mt][nt][half * 2 + 1];
                v0 += __ldg(&bias[col]);
                v1 += __ldg(&bias[col + 1]);
                if (EPI == EPI_RELU_BN) {
                    v0 = fmaxf(v0, 0.0f);
                    v1 = fmaxf(v1, 0.0f);
                    v0 = (v0 - __ldg(&mu[col]))     * rsqrtf(__ldg(&var[col])     + 1e-5f) * __ldg(&gmm[col])     + __ldg(&bet[col]);
                    v1 = (v1 - __ldg(&mu[col + 1])) * rsqrtf(__ldg(&var[col + 1]) + 1e-5f) * __ldg(&gmm[col + 1]) + __ldg(&bet[col + 1]);
                } else if (EPI == EPI_RELU_RES) {
                    float2 rr = *(const float2*)(res + (size_t)m * FDIM + col);
                    v0 = fmaxf(v0, 0.0f) + rr.x;
                    v1 = fmaxf(v1, 0.0f) + rr.y;
                } else if (EPI == EPI_RELU) {
                    v0 = fmaxf(v0, 0.0f);
                    v1 = fmaxf(v1, 0.0f);
                }
                *(float2*)(C + (size_t)m * ldc + col) = make_float2(v0, v1);
            }
        }
    }
}

// ======================= launch =======================
extern "C" void kernel_launch(void* const* d_in, const int* in_sizes, int n_in,
                              void* d_out, int out_size) {
    const float* feat  = (const float*)d_in[0];
    const int*   esrc  = (const int*)d_in[1];
    const int*   edst  = (const int*)d_in[2];
    const float* W1    = (const float*)d_in[3];
    const float* b1    = (const float*)d_in[4];
    const float* gamma = (const float*)d_in[5];
    const float* beta  = (const float*)d_in[6];
    const float* mean  = (const float*)d_in[7];
    const float* var   = (const float*)d_in[8];
    const float* W3    = (const float*)d_in[9];
    const float* b3    = (const float*)d_in[10];
    const float* Wm1   = (const float*)d_in[11];
    const float* bm1   = (const float*)d_in[12];
    const float* Wm2   = (const float*)d_in[13];
    const float* bm2   = (const float*)d_in[14];

    const int n  = in_sizes[0] / FDIM;
    const int ne = in_sizes[1];

    int *deg, *off, *pos, *blk, *csrc;
    float *dinv, *b0, *bb1, *b2, *b3buf, *w1t, *w3t;
    cudaGetSymbolAddress((void**)&deg,  g_deg);
    cudaGetSymbolAddress((void**)&off,  g_off);
    cudaGetSymbolAddress((void**)&pos,  g_pos);
    cudaGetSymbolAddress((void**)&blk,  g_blk);
    cudaGetSymbolAddress((void**)&csrc, g_csrc);
    cudaGetSymbolAddress((void**)&dinv, g_dinv);
    cudaGetSymbolAddress((void**)&b0,   g_b0);
    cudaGetSymbolAddress((void**)&bb1,  g_b1);
    cudaGetSymbolAddress((void**)&b2,   g_b2);
    cudaGetSymbolAddress((void**)&b3buf, g_b3);
    cudaGetSymbolAddress((void**)&w1t,  g_w1t);
    cudaGetSymbolAddress((void**)&w3t,  g_w3t);

    const int nb    = (n + 511) / 512;
    const int agrid = (n + 7) / 8;
    const int ggrid = (n + 127) / 128;

    const int SMEM_N128 = (2 * 128 * 36 + 2 * 128 * 36) * 4;
    const int SMEM_N64  = (2 * 128 * 36 + 2 * 64  * 36) * 4;
    cudaFuncSetAttribute(k_gemm_tc<128, EPI_RELU_BN>,  cudaFuncAttributeMaxDynamicSharedMemorySize, SMEM_N128);
    cudaFuncSetAttribute(k_gemm_tc<128, EPI_RELU_RES>, cudaFuncAttributeMaxDynamicSharedMemorySize, SMEM_N128);
    cudaFuncSetAttribute(k_gemm_tc<128, EPI_RELU>,     cudaFuncAttributeMaxDynamicSharedMemorySize, SMEM_N128);
    cudaFuncSetAttribute(k_gemm_tc<64,  EPI_BIAS>,     cudaFuncAttributeMaxDynamicSharedMemorySize, SMEM_N64);

    // ---- CSR build + weight transforms ----
    cudaMemsetAsync(deg, 0, (size_t)n * sizeof(int));
    k_degi<<<(ne + 255) / 256, 256>>>(edst, ne, deg);
    k_dinvi<<<(n + 255) / 256, 256>>>(deg, dinv, n);
    k_scan1<<<nb, 512>>>(deg, n, off, blk);
    k_scan2p<<<1, 256>>>(blk, nb, off + n);
    k_scan3<<<nb, 512>>>(off, pos, blk, n);
    k_bucket<<<(ne + 255) / 256, 256>>>(esrc, edst, ne, pos, csrc);
    k_wt<<<(128 * 128 + 255) / 256, 256>>>(W1, w1t);
    k_wt<<<(128 * 128 + 255) / 256, 256>>>(W3, w3t);

    // ---- Cheb layer 1: G0 = Ahat(feat), G1 = Ahat(G0) ----
    k_ahat<<<agrid, 256>>>(feat, dinv, off, csrc, bb1, n);
    k_ahat<<<agrid, 256>>>(bb1,  dinv, off, csrc, b2,  n);
    // y = BN(relu([feat|G0|G1] @ W1'^T + b1)) -> b0
    k_gemm_tc<128, EPI_RELU_BN><<<ggrid, 256, SMEM_N128>>>(feat, bb1, b2, n, 384, w1t, b1,
                                                           gamma, beta, mean, var,
                                                           (const float*)nullptr, b0, 128);

    // ---- Cheb layer 2 ----
    k_ahat<<<agrid, 256>>>(b0,  dinv, off, csrc, bb1, n);
    k_ahat<<<agrid, 256>>>(bb1, dinv, off, csrc, b2,  n);
    // x = relu([y|G0'|G1'] @ W3'^T + b3) + y -> b3buf
    k_gemm_tc<128, EPI_RELU_RES><<<ggrid, 256, SMEM_N128>>>(b0, bb1, b2, n, 384, w3t, b3,
                                                            (const float*)nullptr, (const float*)nullptr,
                                                            (const float*)nullptr, (const float*)nullptr,
                                                            b0, b3buf, 128);

    // ---- MLP head ----
    k_gemm_tc<128, EPI_RELU><<<ggrid, 256, SMEM_N128>>>(b3buf, (const float*)nullptr, (const float*)nullptr,
                                                        n, 128, Wm1, bm1,
                                                        (const float*)nullptr, (const float*)nullptr,
                                                        (const float*)nullptr, (const float*)nullptr,
                                                        (const float*)nullptr, bb1, 128);
    k_gemm_tc<64, EPI_BIAS><<<ggrid, 256, SMEM_N64>>>(bb1, (const float*)nullptr, (const float*)nullptr,
                                                      n, 128, Wm2, bm2,
                                                      (const float*)nullptr, (const float*)nullptr,
                                                      (const float*)nullptr, (const float*)nullptr,
                                                      (const float*)nullptr, (float*)d_out, 64);
}

// round 9
// speedup vs baseline: 2.8630x; 1.0263x over previous
#include <cuda_runtime.h>
#include <cstdint>
#include <cstddef>

#define NMAX 100000
#define NEMAX 600000
#define FDIM 128

// ---- static device scratch (no allocations allowed) ----
__device__ int   g_deg[NMAX];
__device__ int   g_off[NMAX + 1];
__device__ int   g_pos[NMAX];
__device__ int   g_blk[256];
__device__ int   g_csrc[NEMAX];
__device__ float g_dinv[NMAX];
__device__ float g_b0[NMAX * FDIM];   // y (layer1 out / residual)
__device__ float g_b1[NMAX * FDIM];   // G0 / reuse
__device__ float g_b2[NMAX * FDIM];   // G1
__device__ float g_b3[NMAX * FDIM];   // m1
__device__ float g_w1t[128 * 384];
__device__ float g_w3t[128 * 384];

__device__ __forceinline__ uint32_t f2tf32(float x) {
    uint32_t r;
    asm("cvt.rna.tf32.f32 %0, %1;" : "=r"(r) : "f"(x));
    return r;
}

// ======================= CSR build =======================
__global__ void k_degi(const int* __restrict__ dst, int ne, int* __restrict__ deg) {
    int i = blockIdx.x * blockDim.x + threadIdx.x;
    if (i < ne) atomicAdd(&deg[dst[i]], 1);
}

// block-local inclusive scan + dinv computation fused
__global__ void k_scan1(const int* __restrict__ deg, int n,
                        int* __restrict__ excl, int* __restrict__ blk,
                        float* __restrict__ dinv) {
    __shared__ int sh[512];
    int tid = threadIdx.x;
    int i = blockIdx.x * 512 + tid;
    int v = (i < n) ? deg[i] : 0;
    if (i < n) dinv[i] = rsqrtf((float)(v > 1 ? v : 1));
    sh[tid] = v;
    __syncthreads();
    #pragma unroll
    for (int ofs = 1; ofs < 512; ofs <<= 1) {
        int t = (tid >= ofs) ? sh[tid - ofs] : 0;
        __syncthreads();
        sh[tid] += t;
        __syncthreads();
    }
    if (i < n) excl[i] = sh[tid] - v;
    if (tid == 511) blk[blockIdx.x] = sh[511];
}

// parallel exclusive scan of block totals (nb <= 256)
__global__ void k_scan2p(int* __restrict__ blk, int nb, int* __restrict__ off_n) {
    __shared__ int sh[256];
    int tid = threadIdx.x;
    int v = (tid < nb) ? blk[tid] : 0;
    sh[tid] = v;
    __syncthreads();
    #pragma unroll
    for (int ofs = 1; ofs < 256; ofs <<= 1) {
        int t = (tid >= ofs) ? sh[tid - ofs] : 0;
        __syncthreads();
        sh[tid] += t;
        __syncthreads();
    }
    if (tid < nb) blk[tid] = sh[tid] - v;
    if (tid == 255) *off_n = sh[255];
}

__global__ void k_scan3(int* __restrict__ off, int* __restrict__ pos,
                        const int* __restrict__ blk, int n) {
    int i = blockIdx.x * 512 + threadIdx.x;
    if (i < n) {
        int o = off[i] + blk[blockIdx.x];
        off[i] = o;
        pos[i] = o;
    }
}

__global__ void k_bucket(const int* __restrict__ src, const int* __restrict__ dst, int ne,
                         int* __restrict__ pos, int* __restrict__ csrc) {
    int e = blockIdx.x * blockDim.x + threadIdx.x;
    if (e < ne) {
        int p = atomicAdd(&pos[dst[e]], 1);
        csrc[p] = src[e];
    }
}

// ======================= weight transform =======================
// W [128,384] = [W0|W1|W2] -> W' = [W0-W1+W2 | W1-4W2 | 2W2]
__global__ void k_wt(const float* __restrict__ W, float* __restrict__ Wt) {
    int i = blockIdx.x * blockDim.x + threadIdx.x;
    if (i >= 128 * 128) return;
    int o = i >> 7, k = i & 127;
    float w0 = W[o * 384 + k];
    float w1 = W[o * 384 + 128 + k];
    float w2 = W[o * 384 + 256 + k];
    Wt[o * 384 + k]       = w0 - w1 + w2;
    Wt[o * 384 + 128 + k] = w1 - 4.0f * w2;
    Wt[o * 384 + 256 + k] = 2.0f * w2;
}

// ======================= pure A_hat application =======================
// Xout[v] = (sum_{s in N(v)} Xin[s]*dinv[s]) * dinv[v]
__global__ void __launch_bounds__(256)
k_ahat(const float* __restrict__ Xin,
       const float* __restrict__ dinv,
       const int* __restrict__ off, const int* __restrict__ csrc,
       float* __restrict__ Xout, int n) {
    int v = blockIdx.x * 8 + (threadIdx.x >> 5);
    if (v >= n) return;
    int lane = threadIdx.x & 31;
    int beg = __ldg(&off[v]);
    int end = __ldg(&off[v + 1]);

    float4 acc = make_float4(0.f, 0.f, 0.f, 0.f);
    int j = beg;
    for (; j + 2 <= end; j += 2) {
        int s0 = __ldg(&csrc[j]);
        int s1 = __ldg(&csrc[j + 1]);
        float c0 = __ldg(&dinv[s0]);
        float c1 = __ldg(&dinv[s1]);
        float4 x0 = *(const float4*)(Xin + (size_t)s0 * FDIM + lane * 4);
        float4 x1 = *(const float4*)(Xin + (size_t)s1 * FDIM + lane * 4);
        acc.x += x0.x * c0 + x1.x * c1;
        acc.y += x0.y * c0 + x1.y * c1;
        acc.z += x0.z * c0 + x1.z * c1;
        acc.w += x0.w * c0 + x1.w * c1;
    }
    if (j < end) {
        int s = __ldg(&csrc[j]);
        float c = __ldg(&dinv[s]);
        float4 x = *(const float4*)(Xin + (size_t)s * FDIM + lane * 4);
        acc.x += x.x * c;
        acc.y += x.y * c;
        acc.z += x.z * c;
        acc.w += x.w * c;
    }
    float dv = __ldg(&dinv[v]);
    float4 r = make_float4(acc.x * dv, acc.y * dv, acc.z * dv, acc.w * dv);
    *(float4*)(Xout + (size_t)v * FDIM + lane * 4) = r;
}

// ============== tf32 mma.sync GEMM: C[256-tile, NT] = [A0|A1|A2] @ W[NT,K]^T + epilogue ==============
// CTA tile 256 x NT, BK=32, 256 threads (8 warps), warp tile 64 x (NT/2), 1 CTA/SM.
// Software-pipelined: global loads staged in registers across the mma block.
#define EPI_BIAS     0
#define EPI_RELU_BN  1
#define EPI_RELU_RES 2
#define EPI_RELU     3

__device__ __forceinline__ void mma8(float c[4], const uint32_t a[4], uint32_t b0, uint32_t b1) {
    asm volatile(
        "mma.sync.aligned.m16n8k8.row.col.f32.tf32.tf32.f32 "
        "{%0,%1,%2,%3}, {%4,%5,%6,%7}, {%8,%9}, {%0,%1,%2,%3};"
        : "+f"(c[0]), "+f"(c[1]), "+f"(c[2]), "+f"(c[3])
        : "r"(a[0]), "r"(a[1]), "r"(a[2]), "r"(a[3]), "r"(b0), "r"(b1));
}

template<int NT, int EPI>
__global__ void __launch_bounds__(256, 1)
k_gemm_tc(const float* __restrict__ A0, const float* __restrict__ A1, const float* __restrict__ A2,
          int M, int K,
          const float* __restrict__ W,
          const float* __restrict__ bias,
          const float* __restrict__ gmm, const float* __restrict__ bet,
          const float* __restrict__ mu,  const float* __restrict__ var,
          const float* __restrict__ res,
          float* __restrict__ C, int ldc) {
    extern __shared__ float sm[];
    float* const AsBase = sm;                     // 2 * 256 * 36
    float* const BsBase = sm + 2 * 256 * 36;      // 2 * NT * 36

    const int tid  = threadIdx.x;
    const int wid  = tid >> 5;
    const int lane = tid & 31;
    const int gID  = lane >> 2;
    const int tig  = lane & 3;
    const int m0   = blockIdx.x * 256;

    const int wm = (wid & 3) * 64;          // 0,64,128,192
    const int wn = (wid >> 2) * (NT / 2);
    constexpr int NTILES = NT / 16;
    constexpr int BITER  = NT / 32;

    float c[4][NTILES][4];
    #pragma unroll
    for (int i = 0; i < 4; i++)
        #pragma unroll
        for (int j = 0; j < NTILES; j++)
            #pragma unroll
            for (int q = 0; q < 4; q++) c[i][j][q] = 0.0f;

    const int nch = K >> 5;

    float4 ra[8];
    float4 rb[BITER];

    auto load_regs = [&](int kt) {
        const float* Ap = (kt < 128) ? A0 : ((kt < 256) ? A1 : A2);
        const int kk = kt & 127;
        #pragma unroll
        for (int it = 0; it < 8; it++) {
            int i = tid + it * 256;
            int row = i >> 3, q = i & 7;
            int gm = m0 + row;
            ra[it] = (gm < M) ? *(const float4*)(Ap + (size_t)gm * FDIM + kk + q * 4)
                              : make_float4(0.f, 0.f, 0.f, 0.f);
        }
        #pragma unroll
        for (int it = 0; it < BITER; it++) {
            int i = tid + it * 256;
            int row = i >> 3, q = i & 7;
            rb[it] = *(const float4*)(W + (size_t)row * K + kt + q * 4);
        }
    };
    auto store_tiles = [&](int buf) {
        float* As = AsBase + buf * (256 * 36);
        float* Bs = BsBase + buf * (NT * 36);
        #pragma unroll
        for (int it = 0; it < 8; it++) {
            int i = tid + it * 256;
            int row = i >> 3, q = i & 7;
            uint4 t = make_uint4(f2tf32(ra[it].x), f2tf32(ra[it].y), f2tf32(ra[it].z), f2tf32(ra[it].w));
            *(uint4*)(As + row * 36 + q * 4) = t;
        }
        #pragma unroll
        for (int it = 0; it < BITER; it++) {
            int i = tid + it * 256;
            int row = i >> 3, q = i & 7;
            uint4 t = make_uint4(f2tf32(rb[it].x), f2tf32(rb[it].y), f2tf32(rb[it].z), f2tf32(rb[it].w));
            *(uint4*)(Bs + row * 36 + q * 4) = t;
        }
    };

    load_regs(0);
    store_tiles(0);
    __syncthreads();

    for (int ch = 0; ch < nch; ch++) {
        const int buf = ch & 1;
        const bool more = (ch + 1 < nch);
        if (more) load_regs((ch + 1) << 5);   // LDGs in flight across the mma block

        const float* As = AsBase + buf * (256 * 36);
        const float* Bs = BsBase + buf * (NT * 36);

        #pragma unroll
        for (int ks = 0; ks < 32; ks += 8) {
            uint32_t a[4][4];
            #pragma unroll
            for (int mt = 0; mt < 4; mt++) {
                const int r = wm + mt * 16 + gID;
                a[mt][0] = __float_as_uint(As[r * 36 + ks + tig]);
                a[mt][1] = __float_as_uint(As[(r + 8) * 36 + ks + tig]);
                a[mt][2] = __float_as_uint(As[r * 36 + ks + tig + 4]);
                a[mt][3] = __float_as_uint(As[(r + 8) * 36 + ks + tig + 4]);
            }
            #pragma unroll
            for (int nt = 0; nt < NTILES; nt++) {
                const int nr = wn + nt * 8 + gID;
                uint32_t b0 = __float_as_uint(Bs[nr * 36 + ks + tig]);
                uint32_t b1 = __float_as_uint(Bs[nr * 36 + ks + tig + 4]);
                #pragma unroll
                for (int mt = 0; mt < 4; mt++)
                    mma8(c[mt][nt], a[mt], b0, b1);
            }
        }
        if (more) store_tiles(buf ^ 1);
        __syncthreads();
    }

    // ---- epilogue ----
    #pragma unroll
    for (int mt = 0; mt < 4; mt++) {
        #pragma unroll
        for (int nt = 0; nt < NTILES; nt++) {
            const int col = wn + nt * 8 + tig * 2;
            #pragma unroll
            for (int half = 0; half < 2; half++) {
                const int m = m0 + wm + mt * 16 + gID + half * 8;
                if (m >= M) continue;
                float v0 = c[mt][nt][half * 2 + 0];
                float v1 = c[mt][nt][half * 2 + 1];
                v0 += __ldg(&bias[col]);
                v1 += __ldg(&bias[col + 1]);
                if (EPI == EPI_RELU_BN) {
                    v0 = fmaxf(v0, 0.0f);
                    v1 = fmaxf(v1, 0.0f);
                    v0 = (v0 - __ldg(&mu[col]))     * rsqrtf(__ldg(&var[col])     + 1e-5f) * __ldg(&gmm[col])     + __ldg(&bet[col]);
                    v1 = (v1 - __ldg(&mu[col + 1])) * rsqrtf(__ldg(&var[col + 1]) + 1e-5f) * __ldg(&gmm[col + 1]) + __ldg(&bet[col + 1]);
                } else if (EPI == EPI_RELU_RES) {
                    float2 rr = *(const float2*)(res + (size_t)m * FDIM + col);
                    v0 = fmaxf(v0, 0.0f) + rr.x;
                    v1 = fmaxf(v1, 0.0f) + rr.y;
                } else if (EPI == EPI_RELU) {
                    v0 = fmaxf(v0, 0.0f);
                    v1 = fmaxf(v1, 0.0f);
                }
                *(float2*)(C + (size_t)m * ldc + col) = make_float2(v0, v1);
            }
        }
    }
}

// ======================= launch =======================
extern "C" void kernel_launch(void* const* d_in, const int* in_sizes, int n_in,
                              void* d_out, int out_size) {
    const float* feat  = (const float*)d_in[0];
    const int*   esrc  = (const int*)d_in[1];
    const int*   edst  = (const int*)d_in[2];
    const float* W1    = (const float*)d_in[3];
    const float* b1    = (const float*)d_in[4];
    const float* gamma = (const float*)d_in[5];
    const float* beta  = (const float*)d_in[6];
    const float* mean  = (const float*)d_in[7];
    const float* var   = (const float*)d_in[8];
    const float* W3    = (const float*)d_in[9];
    const float* b3    = (const float*)d_in[10];
    const float* Wm1   = (const float*)d_in[11];
    const float* bm1   = (const float*)d_in[12];
    const float* Wm2   = (const float*)d_in[13];
    const float* bm2   = (const float*)d_in[14];

    const int n  = in_sizes[0] / FDIM;
    const int ne = in_sizes[1];

    int *deg, *off, *pos, *blk, *csrc;
    float *dinv, *b0, *bb1, *b2, *b3buf, *w1t, *w3t;
    cudaGetSymbolAddress((void**)&deg,  g_deg);
    cudaGetSymbolAddress((void**)&off,  g_off);
    cudaGetSymbolAddress((void**)&pos,  g_pos);
    cudaGetSymbolAddress((void**)&blk,  g_blk);
    cudaGetSymbolAddress((void**)&csrc, g_csrc);
    cudaGetSymbolAddress((void**)&dinv, g_dinv);
    cudaGetSymbolAddress((void**)&b0,   g_b0);
    cudaGetSymbolAddress((void**)&bb1,  g_b1);
    cudaGetSymbolAddress((void**)&b2,   g_b2);
    cudaGetSymbolAddress((void**)&b3buf, g_b3);
    cudaGetSymbolAddress((void**)&w1t,  g_w1t);
    cudaGetSymbolAddress((void**)&w3t,  g_w3t);

    const int nb    = (n + 511) / 512;
    const int agrid = (n + 7) / 8;
    const int ggrid = (n + 255) / 256;

    const int SMEM_N128 = (2 * 256 * 36 + 2 * 128 * 36) * 4;  // 110592
    const int SMEM_N64  = (2 * 256 * 36 + 2 * 64  * 36) * 4;  // 92160
    cudaFuncSetAttribute(k_gemm_tc<128, EPI_RELU_BN>,  cudaFuncAttributeMaxDynamicSharedMemorySize, SMEM_N128);
    cudaFuncSetAttribute(k_gemm_tc<128, EPI_RELU_RES>, cudaFuncAttributeMaxDynamicSharedMemorySize, SMEM_N128);
    cudaFuncSetAttribute(k_gemm_tc<128, EPI_RELU>,     cudaFuncAttributeMaxDynamicSharedMemorySize, SMEM_N128);
    cudaFuncSetAttribute(k_gemm_tc<64,  EPI_BIAS>,     cudaFuncAttributeMaxDynamicSharedMemorySize, SMEM_N64);

    // ---- CSR build + weight transforms ----
    cudaMemsetAsync(deg, 0, (size_t)n * sizeof(int));
    k_degi<<<(ne + 255) / 256, 256>>>(edst, ne, deg);
    k_scan1<<<nb, 512>>>(deg, n, off, blk, dinv);
    k_scan2p<<<1, 256>>>(blk, nb, off + n);
    k_scan3<<<nb, 512>>>(off, pos, blk, n);
    k_bucket<<<(ne + 255) / 256, 256>>>(esrc, edst, ne, pos, csrc);
    k_wt<<<(128 * 128 + 255) / 256, 256>>>(W1, w1t);
    k_wt<<<(128 * 128 + 255) / 256, 256>>>(W3, w3t);

    // ---- Cheb layer 1: G0 = Ahat(feat), G1 = Ahat(G0) ----
    k_ahat<<<agrid, 256>>>(feat, dinv, off, csrc, bb1, n);
    k_ahat<<<agrid, 256>>>(bb1,  dinv, off, csrc, b2,  n);
    k_gemm_tc<128, EPI_RELU_BN><<<ggrid, 256, SMEM_N128>>>(feat, bb1, b2, n, 384, w1t, b1,
                                                           gamma, beta, mean, var,
                                                           (const float*)nullptr, b0, 128);

    // ---- Cheb layer 2 ----
    k_ahat<<<agrid, 256>>>(b0,  dinv, off, csrc, bb1, n);
    k_ahat<<<agrid, 256>>>(bb1, dinv, off, csrc, b2,  n);
    k_gemm_tc<128, EPI_RELU_RES><<<ggrid, 256, SMEM_N128>>>(b0, bb1, b2, n, 384, w3t, b3,
                                                            (const float*)nullptr, (const float*)nullptr,
                                                            (const float*)nullptr, (const float*)nullptr,
                                                            b0, b3buf, 128);

    // ---- MLP head ----
    k_gemm_tc<128, EPI_RELU><<<ggrid, 256, SMEM_N128>>>(b3buf, (const float*)nullptr, (const float*)nullptr,
                                                        n, 128, Wm1, bm1,
                                                        (const float*)nullptr, (const float*)nullptr,
                                                        (const float*)nullptr, (const float*)nullptr,
                                                        (const float*)nullptr, bb1, 128);
    k_gemm_tc<64, EPI_BIAS><<<ggrid, 256, SMEM_N64>>>(bb1, (const float*)nullptr, (const float*)nullptr,
                                                      n, 128, Wm2, bm2,
                                                      (const float*)nullptr, (const float*)nullptr,
                                                      (const float*)nullptr, (const float*)nullptr,
                                                      (const float*)nullptr, (float*)d_out, 64);
}